// round 2
// baseline (speedup 1.0000x reference)
#include <cuda_runtime.h>
#include <cuda_bf16.h>

// LocalFeatureAggregation: B=4, N=16384, K=16, C=64, D=64
// out[b,n,0:64]   = mean_k leakyrelu(geom[b,n,k,:] @ w[d,:] + bias[d])
// out[b,n,64:128] = mean_k features[b, idx[b,n,k], :]
//
// NOTE: neighbor_indices is int32 on device (JAX default x64-disabled
// downcasts the requested int64). Reading it as int64 was the R1 crash.
//
// Block = 4 points x 64 threads (thread = one output channel).
// Gather reads are fully coalesced (64 threads -> one 256B row).

#define BN      65536      // B*N
#define NPTS    16384      // N
#define KNB     16
#define CH      64
#define PTS_PER_BLK 4
#define NTHREADS (PTS_PER_BLK * 64)

__global__ __launch_bounds__(NTHREADS, 8)
void lfa_kernel(const float* __restrict__ features,      // [B,N,64]
                const float* __restrict__ geom,          // [B,N,16,4]
                const float* __restrict__ w,             // [64,4]
                const float* __restrict__ bias,          // [64]
                const int* __restrict__ nbr,             // [B,N,16] int32
                float* __restrict__ out)                 // [B,N,128]
{
    __shared__ float sg[PTS_PER_BLK][KNB * 4];   // geom tile per point
    __shared__ int   sidx[PTS_PER_BLK][KNB];     // neighbor indices per point

    const int tid = threadIdx.x;
    const int lp  = tid >> 6;          // local point 0..3
    const int c   = tid & 63;          // channel 0..63

    const long long g = (long long)blockIdx.x * PTS_PER_BLK + lp;  // global point id
    const int b = (int)(g >> 14);      // g / N   (N = 16384)

    // Stage geom tile (64 floats/point, one per thread) and indices
    sg[lp][c] = geom[g * (KNB * 4) + c];
    if (c < KNB) {
        sidx[lp][c] = nbr[g * KNB + c];
    }
    __syncthreads();

    // --- Part 1: geom MLP + leaky relu + mean over K ---
    const float4 w4 = ((const float4*)w)[c];   // row d=c of w [64,4]
    const float  bb = bias[c];

    float tacc = 0.0f;
    #pragma unroll
    for (int k = 0; k < KNB; k++) {
        float v = fmaf(sg[lp][4*k + 0], w4.x,
                  fmaf(sg[lp][4*k + 1], w4.y,
                  fmaf(sg[lp][4*k + 2], w4.z,
                  fmaf(sg[lp][4*k + 3], w4.w, bb))));
        tacc += (v >= 0.0f) ? v : 0.1f * v;
    }

    // --- Part 2: neighbor-feature gather + mean over K ---
    const float* fb = features + (long long)b * NPTS * CH;
    float facc = 0.0f;
    #pragma unroll
    for (int k = 0; k < KNB; k++) {
        facc += __ldg(fb + (long long)sidx[lp][k] * CH + c);
    }

    // --- Write [D | C] concat, scaled by 1/K ---
    float* op = out + g * (2 * CH);
    op[c]      = tacc * (1.0f / (float)KNB);
    op[CH + c] = facc * (1.0f / (float)KNB);
}

extern "C" void kernel_launch(void* const* d_in, const int* in_sizes, int n_in,
                              void* d_out, int out_size)
{
    const float* features = (const float*)d_in[0];
    const float* geom     = (const float*)d_in[1];
    const float* w        = (const float*)d_in[2];
    const float* bias     = (const float*)d_in[3];
    const int*   nbr      = (const int*)d_in[4];
    float*       out      = (float*)d_out;

    const int nblocks = BN / PTS_PER_BLK;   // 16384
    lfa_kernel<<<nblocks, NTHREADS>>>(features, geom, w, bias, nbr, out);
}

// round 3
// speedup vs baseline: 1.1741x; 1.1741x over previous
#include <cuda_runtime.h>
#include <cuda_bf16.h>

// LocalFeatureAggregation: B=4, N=16384, K=16, C=64, D=64
// out[b,n,0:64]   = mean_k leakyrelu(geom[b,n,k,:] @ w[d,:] + bias[d])
// out[b,n,64:128] = mean_k features[b, idx[b,n,k], :]
//
// R3: vectorized float4 gather. Thread = 4 channels; 16 threads cover a
// 256B feature row with LDG.128 (4x fewer L1 instructions than R2's
// scalar gather, same bytes). Block = 8 points x 16 threads = 128 thr.

#define BN      65536      // B*N
#define NPTS    16384      // N
#define KNB     16
#define CH      64
#define PTS_PER_BLK 8
#define NTHREADS 128

__global__ __launch_bounds__(NTHREADS, 8)
void lfa_kernel(const float* __restrict__ features,      // [B,N,64]
                const float* __restrict__ geom,          // [B,N,16,4]
                const float* __restrict__ w,             // [64,4]
                const float* __restrict__ bias,          // [64]
                const int* __restrict__ nbr,             // [B,N,16] int32
                float* __restrict__ out)                 // [B,N,128]
{
    __shared__ float4 sg[PTS_PER_BLK][KNB];      // geom tile: [point][k] = (x,y,z,w)
    __shared__ int    sidx[PTS_PER_BLK][KNB];    // neighbor indices

    const int tid  = threadIdx.x;
    const int lp   = tid >> 4;          // local point 0..7
    const int l16  = tid & 15;          // lane within point, 0..15
    const long long blk_base = (long long)blockIdx.x * PTS_PER_BLK;

    // Stage geom: block covers 8 points x 16 float4 = 128 float4, one per thread.
    ((float4*)sg)[tid] = ((const float4*)(geom + blk_base * (KNB * 4)))[tid];
    // Stage indices: 128 int32, one per thread.
    ((int*)sidx)[tid] = nbr[blk_base * KNB + tid];
    __syncthreads();

    const long long g = blk_base + lp;          // global point id
    const int b = (int)(g >> 14);               // g / N (N = 16384)

    // --- Part 1: geom MLP (4 output channels per thread) + leakyrelu + mean ---
    const int c4 = l16 * 4;                     // first channel of this thread
    const float4 w0 = ((const float4*)w)[c4 + 0];
    const float4 w1 = ((const float4*)w)[c4 + 1];
    const float4 w2 = ((const float4*)w)[c4 + 2];
    const float4 w3 = ((const float4*)w)[c4 + 3];
    const float4 bb = ((const float4*)bias)[l16];

    float4 tacc = make_float4(0.f, 0.f, 0.f, 0.f);
    #pragma unroll
    for (int k = 0; k < KNB; k++) {
        const float4 gk = sg[lp][k];
        float v0 = fmaf(gk.x, w0.x, fmaf(gk.y, w0.y, fmaf(gk.z, w0.z, fmaf(gk.w, w0.w, bb.x))));
        float v1 = fmaf(gk.x, w1.x, fmaf(gk.y, w1.y, fmaf(gk.z, w1.z, fmaf(gk.w, w1.w, bb.y))));
        float v2 = fmaf(gk.x, w2.x, fmaf(gk.y, w2.y, fmaf(gk.z, w2.z, fmaf(gk.w, w2.w, bb.z))));
        float v3 = fmaf(gk.x, w3.x, fmaf(gk.y, w3.y, fmaf(gk.z, w3.z, fmaf(gk.w, w3.w, bb.w))));
        tacc.x += (v0 >= 0.f) ? v0 : 0.1f * v0;
        tacc.y += (v1 >= 0.f) ? v1 : 0.1f * v1;
        tacc.z += (v2 >= 0.f) ? v2 : 0.1f * v2;
        tacc.w += (v3 >= 0.f) ? v3 : 0.1f * v3;
    }

    // --- Part 2: neighbor gather (float4 per thread, 16 threads = 256B row) ---
    const float4* fb4 = (const float4*)(features + (long long)b * NPTS * CH);
    float4 facc = make_float4(0.f, 0.f, 0.f, 0.f);
    #pragma unroll
    for (int k = 0; k < KNB; k++) {
        const float4 f = __ldg(&fb4[(long long)sidx[lp][k] * (CH / 4) + l16]);
        facc.x += f.x; facc.y += f.y; facc.z += f.z; facc.w += f.w;
    }

    // --- Write [D | C] concat, scaled by 1/K, two STG.128 per thread ---
    const float s = 1.0f / (float)KNB;
    float4* op4 = (float4*)(out + g * (2 * CH));
    op4[l16]      = make_float4(tacc.x * s, tacc.y * s, tacc.z * s, tacc.w * s);
    op4[16 + l16] = make_float4(facc.x * s, facc.y * s, facc.z * s, facc.w * s);
}

extern "C" void kernel_launch(void* const* d_in, const int* in_sizes, int n_in,
                              void* d_out, int out_size)
{
    const float* features = (const float*)d_in[0];
    const float* geom     = (const float*)d_in[1];
    const float* w        = (const float*)d_in[2];
    const float* bias     = (const float*)d_in[3];
    const int*   nbr      = (const int*)d_in[4];
    float*       out      = (float*)d_out;

    const int nblocks = BN / PTS_PER_BLK;   // 8192
    lfa_kernel<<<nblocks, NTHREADS>>>(features, geom, w, bias, nbr, out);
}

// round 4
// speedup vs baseline: 1.2357x; 1.0525x over previous
#include <cuda_runtime.h>
#include <cuda_bf16.h>

// LocalFeatureAggregation: B=4, N=16384, K=16, C=64, D=64
// out[b,n,0:64]   = mean_k leakyrelu(geom[b,n,k,:] @ w[d,:] + bias[d])
// out[b,n,64:128] = mean_k features[b, idx[b,n,k], :]
//
// R4: packed f32x2 (FFMA2) math for the MLP+leaky+accum — halves fma-pipe
// instruction count. Leaky via 0.55v + 0.45|v| (branch-free, packed).
// Gather path unchanged from R3 (LDG.128, 16 threads/row).

#define BN      65536
#define NPTS    16384
#define KNB     16
#define CH      64
#define PTS_PER_BLK 8
#define NTHREADS 128

typedef unsigned long long u64;

__device__ __forceinline__ u64 pack2(float lo, float hi) {
    u64 r; asm("mov.b64 %0, {%1, %2};" : "=l"(r) : "f"(lo), "f"(hi)); return r;
}
__device__ __forceinline__ u64 bcast2(float v) {
    u64 r; asm("mov.b64 %0, {%1, %1};" : "=l"(r) : "f"(v)); return r;
}
__device__ __forceinline__ u64 fma2(u64 a, u64 b, u64 c) {
    u64 d; asm("fma.rn.f32x2 %0, %1, %2, %3;" : "=l"(d) : "l"(a), "l"(b), "l"(c)); return d;
}
__device__ __forceinline__ u64 add2(u64 a, u64 b) {
    u64 d; asm("add.rn.f32x2 %0, %1, %2;" : "=l"(d) : "l"(a), "l"(b)); return d;
}
__device__ __forceinline__ u64 mul2(u64 a, u64 b) {
    u64 d; asm("mul.rn.f32x2 %0, %1, %2;" : "=l"(d) : "l"(a), "l"(b)); return d;
}
__device__ __forceinline__ u64 abs2(u64 a) {
    u64 d; asm("and.b64 %0, %1, 0x7FFFFFFF7FFFFFFF;" : "=l"(d) : "l"(a)); return d;
}

__global__ __launch_bounds__(NTHREADS, 8)
void lfa_kernel(const float* __restrict__ features,      // [B,N,64]
                const float* __restrict__ geom,          // [B,N,16,4]
                const float* __restrict__ w,             // [64,4]
                const float* __restrict__ bias,          // [64]
                const int* __restrict__ nbr,             // [B,N,16] int32
                float* __restrict__ out)                 // [B,N,128]
{
    __shared__ float4 sg[PTS_PER_BLK][KNB];
    __shared__ int    sidx[PTS_PER_BLK][KNB];

    const int tid = threadIdx.x;
    const int lp  = tid >> 4;           // local point 0..7
    const int l16 = tid & 15;           // lane within point
    const long long blk_base = (long long)blockIdx.x * PTS_PER_BLK;

    ((float4*)sg)[tid] = ((const float4*)(geom + blk_base * (KNB * 4)))[tid];
    ((int*)sidx)[tid]  = nbr[blk_base * KNB + tid];
    __syncthreads();

    const long long g = blk_base + lp;
    const int b = (int)(g >> 14);

    // Packed weights for channel pairs (c0,c1) and (c2,c3)
    const int c4 = l16 * 4;
    const float4 w0 = ((const float4*)w)[c4 + 0];
    const float4 w1 = ((const float4*)w)[c4 + 1];
    const float4 w2 = ((const float4*)w)[c4 + 2];
    const float4 w3 = ((const float4*)w)[c4 + 3];
    const float4 bb = ((const float4*)bias)[l16];

    const u64 wx0 = pack2(w0.x, w1.x), wy0 = pack2(w0.y, w1.y);
    const u64 wz0 = pack2(w0.z, w1.z), ww0 = pack2(w0.w, w1.w);
    const u64 wx1 = pack2(w2.x, w3.x), wy1 = pack2(w2.y, w3.y);
    const u64 wz1 = pack2(w2.z, w3.z), ww1 = pack2(w2.w, w3.w);
    const u64 b01 = pack2(bb.x, bb.y), b23 = pack2(bb.z, bb.w);

    const u64 C055 = bcast2(0.55f);
    const u64 C045 = bcast2(0.45f);

    u64 tacc01 = 0, tacc23 = 0;   // bit pattern of (0.f,0.f)
    u64 facc01 = 0, facc23 = 0;

    const float4* fb4 = (const float4*)(features + (long long)b * NPTS * CH);

    #pragma unroll
    for (int k = 0; k < KNB; k++) {
        // --- MLP on packed pairs ---
        const float4 gk = sg[lp][k];
        const u64 gx = bcast2(gk.x), gy = bcast2(gk.y);
        const u64 gz = bcast2(gk.z), gw = bcast2(gk.w);

        u64 v01 = fma2(gx, wx0, fma2(gy, wy0, fma2(gz, wz0, fma2(gw, ww0, b01))));
        u64 v23 = fma2(gx, wx1, fma2(gy, wy1, fma2(gz, wz1, fma2(gw, ww1, b23))));

        // leaky(v) = 0.55*v + 0.45*|v|, fused into accumulator
        tacc01 = fma2(v01, C055, fma2(abs2(v01), C045, tacc01));
        tacc23 = fma2(v23, C055, fma2(abs2(v23), C045, tacc23));

        // --- gather + packed accumulate ---
        const float4 f = __ldg(&fb4[(long long)sidx[lp][k] * (CH / 4) + l16]);
        facc01 = add2(facc01, pack2(f.x, f.y));
        facc23 = add2(facc23, pack2(f.z, f.w));
    }

    // scale by 1/K and store
    const u64 S = bcast2(1.0f / (float)KNB);
    tacc01 = mul2(tacc01, S);  tacc23 = mul2(tacc23, S);
    facc01 = mul2(facc01, S);  facc23 = mul2(facc23, S);

    u64* op = (u64*)(out + g * (2 * CH));
    // out row: [t(64) | f(64)]; this thread's slices at c4 and 64+c4
    op[l16 * 2 + 0]       = tacc01;
    op[l16 * 2 + 1]       = tacc23;
    op[32 + l16 * 2 + 0]  = facc01;
    op[32 + l16 * 2 + 1]  = facc23;
}

extern "C" void kernel_launch(void* const* d_in, const int* in_sizes, int n_in,
                              void* d_out, int out_size)
{
    const float* features = (const float*)d_in[0];
    const float* geom     = (const float*)d_in[1];
    const float* w        = (const float*)d_in[2];
    const float* bias     = (const float*)d_in[3];
    const int*   nbr      = (const int*)d_in[4];
    float*       out      = (float*)d_out;

    const int nblocks = BN / PTS_PER_BLK;   // 8192
    lfa_kernel<<<nblocks, NTHREADS>>>(features, geom, w, bias, nbr, out);
}

// round 6
// speedup vs baseline: 1.2464x; 1.0087x over previous
#include <cuda_runtime.h>
#include <cuda_bf16.h>

// LocalFeatureAggregation: B=4, N=16384, K=16, C=64, D=64
// out[b,n,0:64]   = mean_k leakyrelu(geom[b,n,k,:] @ w[d,:] + b[d])
// out[b,n,64:128] = mean_k features[b, idx[b,n,k], :]
//
// R6 (= R5 + shared-mem alignment fixes): k-pair packed f32x2 with ZERO
// per-iteration packing.
//  - geom staged TRANSPOSED into k-pairs in shared -> LDS.128 yields packed pairs
//  - weights broadcast to pairs once (loop-invariant)
//  - thread = 2 channels, warp = 1 point; gather = LDG.64 feeding add2 directly
//  - leaky(v) = 0.55v + 0.45|v| fused into accumulator (validated R4)

#define BN      65536
#define NPTS    16384
#define KNB     16
#define CH      64
#define PTS_PER_BLK 4
#define NTHREADS 128

typedef unsigned long long u64;

__device__ __forceinline__ u64 pack2(float lo, float hi) {
    u64 r; asm("mov.b64 %0, {%1, %2};" : "=l"(r) : "f"(lo), "f"(hi)); return r;
}
__device__ __forceinline__ void unpack2(float& lo, float& hi, u64 v) {
    asm("mov.b64 {%0, %1}, %2;" : "=f"(lo), "=f"(hi) : "l"(v));
}
__device__ __forceinline__ u64 bcast2(float v) {
    u64 r; asm("mov.b64 %0, {%1, %1};" : "=l"(r) : "f"(v)); return r;
}
__device__ __forceinline__ u64 fma2(u64 a, u64 b, u64 c) {
    u64 d; asm("fma.rn.f32x2 %0, %1, %2, %3;" : "=l"(d) : "l"(a), "l"(b), "l"(c)); return d;
}
__device__ __forceinline__ u64 add2(u64 a, u64 b) {
    u64 d; asm("add.rn.f32x2 %0, %1, %2;" : "=l"(d) : "l"(a), "l"(b)); return d;
}
__device__ __forceinline__ u64 mul2(u64 a, u64 b) {
    u64 d; asm("mul.rn.f32x2 %0, %1, %2;" : "=l"(d) : "l"(a), "l"(b)); return d;
}
__device__ __forceinline__ u64 abs2(u64 a) {
    u64 d; asm("and.b64 %0, %1, 0x7FFFFFFF7FFFFFFF;" : "=l"(d) : "l"(a)); return d;
}

__global__ __launch_bounds__(NTHREADS, 8)
void lfa_kernel(const float* __restrict__ features,      // [B,N,64]
                const float* __restrict__ geom,          // [B,N,16,4]
                const float* __restrict__ w,             // [64,4]
                const float* __restrict__ bias,          // [64]
                const int* __restrict__ nbr,             // [B,N,16] int32
                float* __restrict__ out)                 // [B,N,128]
{
    // Transposed geom: sgt[pt][j][.] = {x_{2j},x_{2j+1}, y.., z.., w..}
    __shared__ __align__(16) float sgt[PTS_PER_BLK][KNB / 2][8];
    __shared__ __align__(8)  int   sidx[PTS_PER_BLK][KNB];

    const int tid = threadIdx.x;
    const long long blk_base = (long long)blockIdx.x * PTS_PER_BLK;

    // Stage: threads 0..63 transpose geom (4 pts x 16 k float4),
    //        threads 64..127 load the 64 neighbor indices.
    if (tid < 64) {
        const int spt = tid >> 4, k = tid & 15;
        const float4 gq = ((const float4*)geom)[blk_base * KNB + tid];
        const int j = k >> 1, i = k & 1;
        sgt[spt][j][0 + i] = gq.x;
        sgt[spt][j][2 + i] = gq.y;
        sgt[spt][j][4 + i] = gq.z;
        sgt[spt][j][6 + i] = gq.w;
    } else {
        ((int*)sidx)[tid - 64] = nbr[blk_base * KNB + (tid - 64)];
    }
    __syncthreads();

    const int lane = tid & 31;          // 0..31 -> channel pair
    const int pt   = tid >> 5;          // warp = point
    const long long g = blk_base + pt;
    const int b = (int)(g >> 14);       // g / N

    // Loop-invariant packed weights (broadcast across the k-pair)
    const float4 wa = ((const float4*)w)[lane * 2 + 0];
    const float4 wb = ((const float4*)w)[lane * 2 + 1];
    const float2 bf = ((const float2*)bias)[lane];

    const u64 w0x = bcast2(wa.x), w0y = bcast2(wa.y), w0z = bcast2(wa.z), w0w = bcast2(wa.w);
    const u64 w1x = bcast2(wb.x), w1y = bcast2(wb.y), w1z = bcast2(wb.z), w1w = bcast2(wb.w);
    const u64 b0  = bcast2(bf.x), b1  = bcast2(bf.y);
    const u64 C055 = bcast2(0.55f), C045 = bcast2(0.45f);

    u64 tacc0 = 0, tacc1 = 0;   // (sum over even k, sum over odd k) per channel
    u64 facc  = 0;              // (sum col c, sum col c+1)

    const u64* fb = (const u64*)(features + (long long)b * NPTS * CH);

    #pragma unroll
    for (int j = 0; j < KNB / 2; j++) {
        // packed geom pairs straight from shared (broadcast within warp)
        const ulonglong2 p0 = *((const ulonglong2*)&sgt[pt][j][0]); // gx2, gy2
        const ulonglong2 p1 = *((const ulonglong2*)&sgt[pt][j][4]); // gz2, gw2

        u64 v0 = fma2(p0.x, w0x, fma2(p0.y, w0y, fma2(p1.x, w0z, fma2(p1.y, w0w, b0))));
        u64 v1 = fma2(p0.x, w1x, fma2(p0.y, w1y, fma2(p1.x, w1z, fma2(p1.y, w1w, b1))));
        tacc0 = fma2(v0, C055, fma2(abs2(v0), C045, tacc0));
        tacc1 = fma2(v1, C055, fma2(abs2(v1), C045, tacc1));

        // gather two rows (k = 2j, 2j+1); LDG.64 feeds add2 directly
        const int2 ij = *((const int2*)&sidx[pt][2 * j]);
        const u64 f0 = __ldg(&fb[(long long)ij.x * (CH / 2) + lane]);
        const u64 f1 = __ldg(&fb[(long long)ij.y * (CH / 2) + lane]);
        facc = add2(facc, add2(f0, f1));
    }

    // reduce k-pair halves, scale by 1/K, store
    const float s = 1.0f / (float)KNB;
    float a0, a1, a2, a3;
    unpack2(a0, a1, tacc0);
    unpack2(a2, a3, tacc1);
    const float t0 = (a0 + a1) * s;
    const float t1 = (a2 + a3) * s;
    facc = mul2(facc, bcast2(s));

    u64* op = (u64*)(out + g * (2 * CH));
    op[lane]      = pack2(t0, t1);   // t channels [2*lane, 2*lane+1]
    op[32 + lane] = facc;            // f channels [64+2*lane, 64+2*lane+1]
}

extern "C" void kernel_launch(void* const* d_in, const int* in_sizes, int n_in,
                              void* d_out, int out_size)
{
    const float* features = (const float*)d_in[0];
    const float* geom     = (const float*)d_in[1];
    const float* w        = (const float*)d_in[2];
    const float* bias     = (const float*)d_in[3];
    const int*   nbr      = (const int*)d_in[4];
    float*       out      = (float*)d_out;

    const int nblocks = BN / PTS_PER_BLK;   // 16384
    lfa_kernel<<<nblocks, NTHREADS>>>(features, geom, w, bias, nbr, out);
}